// round 2
// baseline (speedup 1.0000x reference)
#include <cuda_runtime.h>
#include <math.h>

#define NN 50000
#define NE 600000
#define DD 128
#define NL 4
#define NG 512
#define NT 10
#define EPSF 1e-5f

// ---------------- scratch (static device allocations) ----------------
__device__ int   g_deg[NN];
__device__ int   g_rowptr[NN + 1];
__device__ int   g_cursor[NN];
__device__ int   g_srcperm[NE];
__device__ float g_amp[NN], g_att[NN], g_dinv[NN];
__device__ float g_delta_acc;
__device__ float g_h[NN * DD];
__device__ float g_aggs[(size_t)NN * 4 * DD];   // [N][4*D] : mean|min|max|std
__device__ float g_out[NN * DD];
__device__ float g_bnsum[DD], g_bnsq[DD];
__device__ float g_mu[DD], g_rsg[DD], g_bt[DD];
__device__ int   g_gcnt[NG];
__device__ int   g_goff[NG + 1];
__device__ float g_pool[NG * DD];

// ---------------- small helpers ----------------
__device__ __forceinline__ float4 f4zero() { return make_float4(0.f, 0.f, 0.f, 0.f); }

// ---------------- setup kernels ----------------
__global__ void k_zero() {
    int i = blockIdx.x * blockDim.x + threadIdx.x;
    if (i < NN) { g_deg[i] = 0; g_cursor[i] = 0; }
    if (i < NG) g_gcnt[i] = 0;
    if (i == 0) g_delta_acc = 0.f;
}

__global__ void k_hist(const int* __restrict__ ei, const int* __restrict__ batch) {
    int e = blockIdx.x * blockDim.x + threadIdx.x;
    if (e < NE) atomicAdd(&g_deg[ei[NE + e]], 1);     // dst row
    if (e < NN) atomicAdd(&g_gcnt[batch[e]], 1);
}

__global__ void k_scan() {
    __shared__ int s[1024];
    int t = threadIdx.x;
    const int C = (NN + 1023) / 1024;
    int base = t * C;
    int acc = 0;
    for (int c = 0; c < C; c++) { int i = base + c; if (i < NN) acc += g_deg[i]; }
    s[t] = acc;
    __syncthreads();
    for (int d = 1; d < 1024; d <<= 1) {
        int add = (t >= d) ? s[t - d] : 0;
        __syncthreads();
        s[t] += add;
        __syncthreads();
    }
    int off = s[t] - acc;
    for (int c = 0; c < C; c++) { int i = base + c; if (i < NN) { g_rowptr[i] = off; off += g_deg[i]; } }
    if (t == 0) g_rowptr[NN] = NE;
    __syncthreads();
    int v = (t < NG) ? g_gcnt[t] : 0;
    s[t] = v;
    __syncthreads();
    for (int d = 1; d < 1024; d <<= 1) {
        int add = (t >= d) ? s[t - d] : 0;
        __syncthreads();
        s[t] += add;
        __syncthreads();
    }
    if (t < NG) g_goff[t] = s[t] - v;
    if (t == 0) g_goff[NG] = NN;
}

__global__ void k_delta() {
    int i = blockIdx.x * blockDim.x + threadIdx.x;
    float v = (i < NN) ? log1pf((float)g_deg[i]) : 0.f;
    for (int o = 16; o; o >>= 1) v += __shfl_down_sync(0xffffffffu, v, o);
    __shared__ float ws[8];
    if ((threadIdx.x & 31) == 0) ws[threadIdx.x >> 5] = v;
    __syncthreads();
    if (threadIdx.x < 8) {
        v = ws[threadIdx.x];
        for (int o = 4; o; o >>= 1) v += __shfl_down_sync(0xffu, v, o);
        if (threadIdx.x == 0) atomicAdd(&g_delta_acc, v);
    }
}

__global__ void k_scalars() {
    int i = blockIdx.x * blockDim.x + threadIdx.x;
    if (i >= NN) return;
    float deg = (float)g_deg[i];
    float d = fmaxf(deg, 1.f);
    float ld = log1pf(d);
    float delta = g_delta_acc / (float)NN;
    g_amp[i] = ld / delta;
    g_att[i] = delta / ld;
    g_dinv[i] = 1.f / d;
}

__global__ void k_scatter(const int* __restrict__ ei) {
    int e = blockIdx.x * blockDim.x + threadIdx.x;
    if (e >= NE) return;
    int dst = ei[NE + e];
    int p = atomicAdd(&g_cursor[dst], 1);
    g_srcperm[g_rowptr[dst] + p] = ei[e];
}

__global__ void k_emb(const float* __restrict__ x, const float* __restrict__ W,
                      const float* __restrict__ b) {
    int t = blockIdx.x * blockDim.x + threadIdx.x;
    int i = t >> 5, c = t & 31;
    if (i >= NN) return;
    float x0 = x[i * 3 + 0], x1 = x[i * 3 + 1], x2 = x[i * 3 + 2];
    float4 w0 = *(const float4*)&W[0 * DD + c * 4];
    float4 w1 = *(const float4*)&W[1 * DD + c * 4];
    float4 w2 = *(const float4*)&W[2 * DD + c * 4];
    float4 bb = *(const float4*)&b[c * 4];
    float4 h;
    h.x = bb.x + x0 * w0.x + x1 * w1.x + x2 * w2.x;
    h.y = bb.y + x0 * w0.y + x1 * w1.y + x2 * w2.y;
    h.z = bb.z + x0 * w0.z + x1 * w1.z + x2 * w2.z;
    h.w = bb.w + x0 * w0.w + x1 * w1.w + x2 * w2.w;
    ((float4*)g_h)[i * 32 + c] = h;
}

// ---------------- per-layer kernels ----------------
__global__ void k_agg() {
    int warp = (blockIdx.x * blockDim.x + threadIdx.x) >> 5;
    int lane = threadIdx.x & 31;
    if (warp >= NN) return;
    int beg = g_rowptr[warp], end = g_rowptr[warp + 1];
    float4 s1 = f4zero(), s2 = f4zero();
    float4 mn = make_float4(INFINITY, INFINITY, INFINITY, INFINITY);
    float4 mx = make_float4(-INFINITY, -INFINITY, -INFINITY, -INFINITY);
    const float4* hp = (const float4*)g_h;
    for (int e = beg; e < end; e += 32) {
        int myj = (e + lane < end) ? g_srcperm[e + lane] : 0;
        int cnt = min(32, end - e);
        for (int kk = 0; kk < cnt; kk++) {
            int j = __shfl_sync(0xffffffffu, myj, kk);
            float4 m = hp[j * 32 + lane];
            s1.x += m.x; s1.y += m.y; s1.z += m.z; s1.w += m.w;
            s2.x += m.x * m.x; s2.y += m.y * m.y; s2.z += m.z * m.z; s2.w += m.w * m.w;
            mn.x = fminf(mn.x, m.x); mn.y = fminf(mn.y, m.y); mn.z = fminf(mn.z, m.z); mn.w = fminf(mn.w, m.w);
            mx.x = fmaxf(mx.x, m.x); mx.y = fmaxf(mx.y, m.y); mx.z = fmaxf(mx.z, m.z); mx.w = fmaxf(mx.w, m.w);
        }
    }
    float dinv = g_dinv[warp];
    float4 mean, sd;
    mean.x = s1.x * dinv; mean.y = s1.y * dinv; mean.z = s1.z * dinv; mean.w = s1.w * dinv;
    sd.x = sqrtf(fmaxf(s2.x * dinv - mean.x * mean.x, 0.f) + EPSF);
    sd.y = sqrtf(fmaxf(s2.y * dinv - mean.y * mean.y, 0.f) + EPSF);
    sd.z = sqrtf(fmaxf(s2.z * dinv - mean.z * mean.z, 0.f) + EPSF);
    sd.w = sqrtf(fmaxf(s2.w * dinv - mean.w * mean.w, 0.f) + EPSF);
    if (beg == end) { mn = f4zero(); mx = f4zero(); }
    float4* A = (float4*)(g_aggs + (size_t)warp * 4 * DD);
    A[0 * 32 + lane] = mean;
    A[1 * 32 + lane] = mn;
    A[2 * 32 + lane] = mx;
    A[3 * 32 + lane] = sd;
}

#define BM 128
#define BN 128
#define BK 16
__global__ __launch_bounds__(256) void k_gemm(const float* __restrict__ Wl,
                                              const float* __restrict__ bl) {
    __shared__ float sA[BK][BM];
    __shared__ float sB[BK][BN];
    __shared__ float sAmp[BM], sAtt[BM];
    int bm = blockIdx.x * BM;
    int tid = threadIdx.x;
    if (tid < BM) {
        int r = bm + tid;
        sAmp[tid] = (r < NN) ? g_amp[r] : 0.f;
        sAtt[tid] = (r < NN) ? g_att[r] : 0.f;
    }
    // zero BN accumulators for the following stats kernel (stream-ordered)
    if (blockIdx.x == 0 && tid < DD) { g_bnsum[tid] = 0.f; g_bnsq[tid] = 0.f; }
    __syncthreads();
    int tx = tid & 15, ty = tid >> 4;
    float acc[8][8];
#pragma unroll
    for (int i = 0; i < 8; i++)
#pragma unroll
        for (int j = 0; j < 8; j++) acc[i][j] = 0.f;

    for (int k0 = 0; k0 < 1536; k0 += BK) {
        int slab = k0 >> 9;
#pragma unroll
        for (int u = 0; u < 2; u++) {
            int idx = tid + u * 256;     // 0..511 float4 slots
            int m = idx >> 2;
            int k4 = idx & 3;
            int row = bm + m;
            float4 a = (row < NN)
                ? *(const float4*)&g_aggs[(size_t)row * 512 + (k0 & 511) + k4 * 4]
                : f4zero();
            float sc = (slab == 0) ? 1.f : ((slab == 1) ? sAmp[m] : sAtt[m]);
            sA[k4 * 4 + 0][m] = a.x * sc;
            sA[k4 * 4 + 1][m] = a.y * sc;
            sA[k4 * 4 + 2][m] = a.z * sc;
            sA[k4 * 4 + 3][m] = a.w * sc;
        }
#pragma unroll
        for (int u = 0; u < 2; u++) {
            int idx = tid + u * 256;
            int k = idx >> 5;
            int n4 = idx & 31;
            *(float4*)&sB[k][n4 * 4] = *(const float4*)&Wl[(k0 + k) * DD + n4 * 4];
        }
        __syncthreads();
#pragma unroll
        for (int k = 0; k < BK; k++) {
            float4 a0 = *(const float4*)&sA[k][ty * 8];
            float4 a1 = *(const float4*)&sA[k][ty * 8 + 4];
            float4 b0 = *(const float4*)&sB[k][tx * 8];
            float4 b1 = *(const float4*)&sB[k][tx * 8 + 4];
            float af[8] = {a0.x, a0.y, a0.z, a0.w, a1.x, a1.y, a1.z, a1.w};
            float bf[8] = {b0.x, b0.y, b0.z, b0.w, b1.x, b1.y, b1.z, b1.w};
#pragma unroll
            for (int i = 0; i < 8; i++)
#pragma unroll
                for (int j = 0; j < 8; j++) acc[i][j] += af[i] * bf[j];
        }
        __syncthreads();
    }
#pragma unroll
    for (int i = 0; i < 8; i++) {
        int row = bm + ty * 8 + i;
        if (row < NN) {
#pragma unroll
            for (int j = 0; j < 8; j++)
                g_out[(size_t)row * DD + tx * 8 + j] = acc[i][j] + bl[tx * 8 + j];
        }
    }
}

__global__ void k_bnstats() {
    int f = threadIdx.x;            // 128 threads
    int r0 = blockIdx.x * 256;
    int r1 = min(r0 + 256, NN);
    float s = 0.f, q = 0.f;
    for (int r = r0; r < r1; r++) {
        float v = g_out[(size_t)r * DD + f];
        s += v; q += v * v;
    }
    atomicAdd(&g_bnsum[f], s);
    atomicAdd(&g_bnsq[f], q);
}

__global__ void k_bnfin(const float* __restrict__ gamma, const float* __restrict__ beta) {
    int f = threadIdx.x;
    float mu = g_bnsum[f] / (float)NN;
    float var = g_bnsq[f] / (float)NN - mu * mu;
    float rs = rsqrtf(var + EPSF);
    g_mu[f] = mu;
    g_rsg[f] = rs * gamma[f];
    g_bt[f] = beta[f];
}

__global__ void k_bnapply() {
    int t = blockIdx.x * blockDim.x + threadIdx.x;
    if (t >= NN * 32) return;
    int c = (t & 31) * 4;
    float4 o = ((const float4*)g_out)[t];
    float4 h = ((float4*)g_h)[t];
    o.x = fmaxf((o.x - g_mu[c + 0]) * g_rsg[c + 0] + g_bt[c + 0], 0.f) + h.x;
    o.y = fmaxf((o.y - g_mu[c + 1]) * g_rsg[c + 1] + g_bt[c + 1], 0.f) + h.y;
    o.z = fmaxf((o.z - g_mu[c + 2]) * g_rsg[c + 2] + g_bt[c + 2], 0.f) + h.z;
    o.w = fmaxf((o.w - g_mu[c + 3]) * g_rsg[c + 3] + g_bt[c + 3], 0.f) + h.w;
    ((float4*)g_h)[t] = o;
}

// ---------------- pooling + MLP ----------------
__global__ void k_pool() {
    int warp = (blockIdx.x * blockDim.x + threadIdx.x) >> 5;
    int lane = threadIdx.x & 31;
    if (warp >= NG) return;
    int beg = g_goff[warp], end = g_goff[warp + 1];
    float4 s = f4zero();
    const float4* hp = (const float4*)g_h;
    for (int r = beg; r < end; r++) {
        float4 v = hp[r * 32 + lane];
        s.x += v.x; s.y += v.y; s.z += v.z; s.w += v.w;
    }
    float inv = 1.f / (float)max(end - beg, 1);
    s.x *= inv; s.y *= inv; s.z *= inv; s.w *= inv;
    ((float4*)g_pool)[warp * 32 + lane] = s;
}

__global__ void k_mlp(const float* __restrict__ W1, const float* __restrict__ b1,
                      const float* __restrict__ W2, const float* __restrict__ b2,
                      const float* __restrict__ W3, const float* __restrict__ b3,
                      float* __restrict__ out) {
    __shared__ float sg[DD], sz1[64], sz2[32];
    int gid = blockIdx.x;
    int tid = threadIdx.x;      // 128
    sg[tid] = g_pool[gid * DD + tid];
    __syncthreads();
    if (tid < 64) {
        float a = b1[tid];
        for (int k = 0; k < DD; k++) a += sg[k] * W1[k * 64 + tid];
        sz1[tid] = fmaxf(a, 0.f);
    }
    __syncthreads();
    if (tid < 32) {
        float a = b2[tid];
        for (int k = 0; k < 64; k++) a += sz1[k] * W2[k * 32 + tid];
        sz2[tid] = fmaxf(a, 0.f);
    }
    __syncthreads();
    if (tid < NT) {
        float a = b3[tid];
        for (int k = 0; k < 32; k++) a += sz2[k] * W3[k * NT + tid];
        out[gid * NT + tid] = a;
    }
}

// ---------------- launch ----------------
extern "C" void kernel_launch(void* const* d_in, const int* in_sizes, int n_in,
                              void* d_out, int out_size) {
    const float* x      = (const float*)d_in[0];
    const int*   ei     = (const int*)d_in[1];
    const int*   batch  = (const int*)d_in[2];
    const float* emb_W  = (const float*)d_in[3];
    const float* emb_b  = (const float*)d_in[4];
    const float* conv_W = (const float*)d_in[5];
    const float* conv_b = (const float*)d_in[6];
    const float* bng    = (const float*)d_in[7];
    const float* bnb    = (const float*)d_in[8];
    const float* W1     = (const float*)d_in[9];
    const float* b1     = (const float*)d_in[10];
    const float* W2     = (const float*)d_in[11];
    const float* b2     = (const float*)d_in[12];
    const float* W3     = (const float*)d_in[13];
    const float* b3     = (const float*)d_in[14];
    float* out = (float*)d_out;

    k_zero<<<(NN + 255) / 256, 256>>>();
    k_hist<<<(NE + 255) / 256, 256>>>(ei, batch);
    k_scan<<<1, 1024>>>();
    k_delta<<<(NN + 255) / 256, 256>>>();
    k_scalars<<<(NN + 255) / 256, 256>>>();
    k_scatter<<<(NE + 255) / 256, 256>>>(ei);
    k_emb<<<(NN * 32 + 255) / 256, 256>>>(x, emb_W, emb_b);

    for (int l = 0; l < NL; l++) {
        k_agg<<<(NN * 32 + 255) / 256, 256>>>();
        k_gemm<<<(NN + BM - 1) / BM, 256>>>(conv_W + (size_t)l * 12 * DD * DD,
                                            conv_b + (size_t)l * DD);
        k_bnstats<<<(NN + 255) / 256, DD>>>();
        k_bnfin<<<1, DD>>>(bng + (size_t)l * DD, bnb + (size_t)l * DD);
        k_bnapply<<<(NN * 32 + 255) / 256, 256>>>();
    }

    k_pool<<<(NG * 32 + 255) / 256, 256>>>();
    k_mlp<<<NG, DD>>>(W1, b1, W2, b2, W3, b3, out);
}

// round 3
// speedup vs baseline: 1.6607x; 1.6607x over previous
#include <cuda_runtime.h>
#include <math.h>

#define NN 50000
#define NE 600000
#define DD 128
#define NL 4
#define NG 512
#define NT 10
#define EPSF 1e-5f

// ---------------- scratch (static device allocations) ----------------
__device__ int   g_deg[NN];
__device__ int   g_rowptr[NN + 1];
__device__ int   g_cursor[NN];
__device__ int   g_srcperm[NE];
__device__ float g_amp[NN], g_att[NN], g_dinv[NN];
__device__ float g_delta_acc;
__device__ float g_h[NN * DD];
__device__ float g_aggs[(size_t)NN * 4 * DD];   // [N][4*D] : mean|min|max|std
__device__ float g_out[NN * DD];
__device__ float g_bnsum[DD], g_bnsq[DD];
__device__ float g_mu[DD], g_rsg[DD], g_bt[DD];
__device__ int   g_gcnt[NG];
__device__ int   g_goff[NG + 1];
__device__ float g_pool[NG * DD];

// ---------------- small helpers ----------------
__device__ __forceinline__ float4 f4zero() { return make_float4(0.f, 0.f, 0.f, 0.f); }

__device__ __forceinline__ unsigned f2tf(float f) {
    unsigned u;
    asm("cvt.rna.tf32.f32 %0, %1;" : "=r"(u) : "f"(f));
    return u;
}

// ---------------- setup kernels ----------------
__global__ void k_zero() {
    int i = blockIdx.x * blockDim.x + threadIdx.x;
    if (i < NN) { g_deg[i] = 0; g_cursor[i] = 0; }
    if (i < NG) g_gcnt[i] = 0;
    if (i == 0) g_delta_acc = 0.f;
}

__global__ void k_hist(const int* __restrict__ ei, const int* __restrict__ batch) {
    int e = blockIdx.x * blockDim.x + threadIdx.x;
    if (e < NE) atomicAdd(&g_deg[ei[NE + e]], 1);     // dst row
    if (e < NN) atomicAdd(&g_gcnt[batch[e]], 1);
}

__global__ void k_scan() {
    __shared__ int s[1024];
    int t = threadIdx.x;
    const int C = (NN + 1023) / 1024;
    int base = t * C;
    int acc = 0;
    for (int c = 0; c < C; c++) { int i = base + c; if (i < NN) acc += g_deg[i]; }
    s[t] = acc;
    __syncthreads();
    for (int d = 1; d < 1024; d <<= 1) {
        int add = (t >= d) ? s[t - d] : 0;
        __syncthreads();
        s[t] += add;
        __syncthreads();
    }
    int off = s[t] - acc;
    for (int c = 0; c < C; c++) { int i = base + c; if (i < NN) { g_rowptr[i] = off; off += g_deg[i]; } }
    if (t == 0) g_rowptr[NN] = NE;
    __syncthreads();
    int v = (t < NG) ? g_gcnt[t] : 0;
    s[t] = v;
    __syncthreads();
    for (int d = 1; d < 1024; d <<= 1) {
        int add = (t >= d) ? s[t - d] : 0;
        __syncthreads();
        s[t] += add;
        __syncthreads();
    }
    if (t < NG) g_goff[t] = s[t] - v;
    if (t == 0) g_goff[NG] = NN;
}

__global__ void k_delta() {
    int i = blockIdx.x * blockDim.x + threadIdx.x;
    float v = (i < NN) ? log1pf((float)g_deg[i]) : 0.f;
    for (int o = 16; o; o >>= 1) v += __shfl_down_sync(0xffffffffu, v, o);
    __shared__ float ws[8];
    if ((threadIdx.x & 31) == 0) ws[threadIdx.x >> 5] = v;
    __syncthreads();
    if (threadIdx.x < 8) {
        v = ws[threadIdx.x];
        for (int o = 4; o; o >>= 1) v += __shfl_down_sync(0xffu, v, o);
        if (threadIdx.x == 0) atomicAdd(&g_delta_acc, v);
    }
}

__global__ void k_scalars() {
    int i = blockIdx.x * blockDim.x + threadIdx.x;
    if (i >= NN) return;
    float deg = (float)g_deg[i];
    float d = fmaxf(deg, 1.f);
    float ld = log1pf(d);
    float delta = g_delta_acc / (float)NN;
    g_amp[i] = ld / delta;
    g_att[i] = delta / ld;
    g_dinv[i] = 1.f / d;
}

__global__ void k_scatter(const int* __restrict__ ei) {
    int e = blockIdx.x * blockDim.x + threadIdx.x;
    if (e >= NE) return;
    int dst = ei[NE + e];
    int p = atomicAdd(&g_cursor[dst], 1);
    g_srcperm[g_rowptr[dst] + p] = ei[e];
}

__global__ void k_emb(const float* __restrict__ x, const float* __restrict__ W,
                      const float* __restrict__ b) {
    int t = blockIdx.x * blockDim.x + threadIdx.x;
    int i = t >> 5, c = t & 31;
    if (i >= NN) return;
    float x0 = x[i * 3 + 0], x1 = x[i * 3 + 1], x2 = x[i * 3 + 2];
    float4 w0 = *(const float4*)&W[0 * DD + c * 4];
    float4 w1 = *(const float4*)&W[1 * DD + c * 4];
    float4 w2 = *(const float4*)&W[2 * DD + c * 4];
    float4 bb = *(const float4*)&b[c * 4];
    float4 h;
    h.x = bb.x + x0 * w0.x + x1 * w1.x + x2 * w2.x;
    h.y = bb.y + x0 * w0.y + x1 * w1.y + x2 * w2.y;
    h.z = bb.z + x0 * w0.z + x1 * w1.z + x2 * w2.z;
    h.w = bb.w + x0 * w0.w + x1 * w1.w + x2 * w2.w;
    ((float4*)g_h)[i * 32 + c] = h;
}

// ---------------- per-layer kernels ----------------
__global__ void k_agg() {
    int warp = (blockIdx.x * blockDim.x + threadIdx.x) >> 5;
    int lane = threadIdx.x & 31;
    if (warp >= NN) return;
    int beg = g_rowptr[warp], end = g_rowptr[warp + 1];
    float4 s1 = f4zero(), s2 = f4zero();
    float4 mn = make_float4(INFINITY, INFINITY, INFINITY, INFINITY);
    float4 mx = make_float4(-INFINITY, -INFINITY, -INFINITY, -INFINITY);
    const float4* hp = (const float4*)g_h;
    for (int e = beg; e < end; e += 32) {
        int myj = (e + lane < end) ? g_srcperm[e + lane] : 0;
        int cnt = min(32, end - e);
        for (int kk = 0; kk < cnt; kk++) {
            int j = __shfl_sync(0xffffffffu, myj, kk);
            float4 m = hp[j * 32 + lane];
            s1.x += m.x; s1.y += m.y; s1.z += m.z; s1.w += m.w;
            s2.x += m.x * m.x; s2.y += m.y * m.y; s2.z += m.z * m.z; s2.w += m.w * m.w;
            mn.x = fminf(mn.x, m.x); mn.y = fminf(mn.y, m.y); mn.z = fminf(mn.z, m.z); mn.w = fminf(mn.w, m.w);
            mx.x = fmaxf(mx.x, m.x); mx.y = fmaxf(mx.y, m.y); mx.z = fmaxf(mx.z, m.z); mx.w = fmaxf(mx.w, m.w);
        }
    }
    float dinv = g_dinv[warp];
    float4 mean, sd;
    mean.x = s1.x * dinv; mean.y = s1.y * dinv; mean.z = s1.z * dinv; mean.w = s1.w * dinv;
    sd.x = sqrtf(fmaxf(s2.x * dinv - mean.x * mean.x, 0.f) + EPSF);
    sd.y = sqrtf(fmaxf(s2.y * dinv - mean.y * mean.y, 0.f) + EPSF);
    sd.z = sqrtf(fmaxf(s2.z * dinv - mean.z * mean.z, 0.f) + EPSF);
    sd.w = sqrtf(fmaxf(s2.w * dinv - mean.w * mean.w, 0.f) + EPSF);
    if (beg == end) { mn = f4zero(); mx = f4zero(); }
    float4* A = (float4*)(g_aggs + (size_t)warp * 4 * DD);
    A[0 * 32 + lane] = mean;
    A[1 * 32 + lane] = mn;
    A[2 * 32 + lane] = mx;
    A[3 * 32 + lane] = sd;
}

// ---------------- TF32 tensor-core GEMM ----------------
// C[128 x 128] tile per block; 8 warps each compute 64x32 via m16n8k8 mma.
#define BM 128
#define BK 16
#define SSTRIDE 20          // 16 + 4 pad: fragment LDS hits all 32 banks

__global__ __launch_bounds__(256) void k_gemm(const float* __restrict__ Wl,
                                              const float* __restrict__ bl) {
    __shared__ unsigned sA[BM * SSTRIDE];   // [m][k], tf32 bits
    __shared__ unsigned sB[DD * SSTRIDE];   // [n][k], tf32 bits
    __shared__ float sAmp[BM], sAtt[BM], sBias[DD];

    int bm = blockIdx.x * BM;
    int tid = threadIdx.x;
    int lane = tid & 31;
    int warp = tid >> 5;
    int g = lane >> 2;      // group id (row within 8)
    int t = lane & 3;       // thread-in-group (k within 4)
    int wm = warp >> 2;     // 0..1 -> m_base = wm*64
    int wn = warp & 3;      // 0..3 -> n_base = wn*32
    int m_base = wm * 64;
    int n_base = wn * 32;

    if (tid < BM) {
        int r = bm + tid;
        sAmp[tid] = (r < NN) ? g_amp[r] : 0.f;
        sAtt[tid] = (r < NN) ? g_att[r] : 0.f;
        sBias[tid] = bl[tid];
    }
    if (blockIdx.x == 0 && tid < DD) { g_bnsum[tid] = 0.f; g_bnsq[tid] = 0.f; }
    __syncthreads();

    float acc[4][4][4];
#pragma unroll
    for (int i = 0; i < 4; i++)
#pragma unroll
        for (int j = 0; j < 4; j++)
#pragma unroll
            for (int c = 0; c < 4; c++) acc[i][j][c] = 0.f;

    // per-chunk load descriptors (2 float4 of A, 2 float4 of B per thread)
    //   A: idx = tid + u*256 ; m = idx>>2, k4 = idx&3
    //   B: idx = tid + u*256 ; k = idx>>5, n4 = idx&31
    float4 aR[2], bR[2];
    const int aM[2] = { (tid) >> 2, (tid + 256) >> 2 };
    const int aK4[2] = { tid & 3, (tid + 256) & 3 };
    const int bK[2] = { tid >> 5, (tid + 256) >> 5 };
    const int bN4[2] = { tid & 31, (tid + 256) & 31 };

    const int NCHUNK = 1536 / BK;   // 96

    auto loadChunk = [&](int chunk) {
        int kg0 = chunk * BK;
        int koff = kg0 & 511;
#pragma unroll
        for (int u = 0; u < 2; u++) {
            int row = bm + aM[u];
            aR[u] = (row < NN)
                ? *(const float4*)&g_aggs[(size_t)row * 512 + koff + aK4[u] * 4]
                : f4zero();
            bR[u] = *(const float4*)&Wl[(size_t)(kg0 + bK[u]) * DD + bN4[u] * 4];
        }
    };
    auto storeChunk = [&](int chunk) {
        int slab = (chunk * BK) >> 9;   // 0,1,2 (BK divides 512)
#pragma unroll
        for (int u = 0; u < 2; u++) {
            int m = aM[u];
            float sc = (slab == 0) ? 1.f : ((slab == 1) ? sAmp[m] : sAtt[m]);
            unsigned* pa = &sA[m * SSTRIDE + aK4[u] * 4];
            pa[0] = f2tf(aR[u].x * sc);
            pa[1] = f2tf(aR[u].y * sc);
            pa[2] = f2tf(aR[u].z * sc);
            pa[3] = f2tf(aR[u].w * sc);
            int n0 = bN4[u] * 4, kk = bK[u];
            sB[(n0 + 0) * SSTRIDE + kk] = f2tf(bR[u].x);
            sB[(n0 + 1) * SSTRIDE + kk] = f2tf(bR[u].y);
            sB[(n0 + 2) * SSTRIDE + kk] = f2tf(bR[u].z);
            sB[(n0 + 3) * SSTRIDE + kk] = f2tf(bR[u].w);
        }
    };

    loadChunk(0);
    storeChunk(0);
    __syncthreads();

    for (int chunk = 0; chunk < NCHUNK; chunk++) {
        if (chunk + 1 < NCHUNK) loadChunk(chunk + 1);

#pragma unroll
        for (int ks = 0; ks < BK; ks += 8) {
            unsigned bfrag[4][2];
#pragma unroll
            for (int j = 0; j < 4; j++) {
                int n = n_base + j * 8 + g;
                bfrag[j][0] = sB[n * SSTRIDE + ks + t];
                bfrag[j][1] = sB[n * SSTRIDE + ks + t + 4];
            }
#pragma unroll
            for (int i = 0; i < 4; i++) {
                int m0 = m_base + i * 16 + g;
                unsigned a0 = sA[m0 * SSTRIDE + ks + t];
                unsigned a1 = sA[(m0 + 8) * SSTRIDE + ks + t];
                unsigned a2 = sA[m0 * SSTRIDE + ks + t + 4];
                unsigned a3 = sA[(m0 + 8) * SSTRIDE + ks + t + 4];
#pragma unroll
                for (int j = 0; j < 4; j++) {
                    asm volatile(
                        "mma.sync.aligned.m16n8k8.row.col.f32.tf32.tf32.f32 "
                        "{%0,%1,%2,%3}, {%4,%5,%6,%7}, {%8,%9}, {%0,%1,%2,%3};"
                        : "+f"(acc[i][j][0]), "+f"(acc[i][j][1]),
                          "+f"(acc[i][j][2]), "+f"(acc[i][j][3])
                        : "r"(a0), "r"(a1), "r"(a2), "r"(a3),
                          "r"(bfrag[j][0]), "r"(bfrag[j][1]));
                }
            }
        }
        __syncthreads();
        if (chunk + 1 < NCHUNK) {
            storeChunk(chunk + 1);
            __syncthreads();
        }
    }

    // epilogue: add bias, store (c0,c1 are adjacent columns -> float2)
#pragma unroll
    for (int i = 0; i < 4; i++) {
        int r0 = bm + m_base + i * 16 + g;
        int r1 = r0 + 8;
#pragma unroll
        for (int j = 0; j < 4; j++) {
            int col = n_base + j * 8 + t * 2;
            float bx = sBias[col], by = sBias[col + 1];
            if (r0 < NN) {
                float2 v = make_float2(acc[i][j][0] + bx, acc[i][j][1] + by);
                *(float2*)&g_out[(size_t)r0 * DD + col] = v;
            }
            if (r1 < NN) {
                float2 v = make_float2(acc[i][j][2] + bx, acc[i][j][3] + by);
                *(float2*)&g_out[(size_t)r1 * DD + col] = v;
            }
        }
    }
}

__global__ void k_bnstats() {
    int f = threadIdx.x;            // 128 threads
    int r0 = blockIdx.x * 256;
    int r1 = min(r0 + 256, NN);
    float s = 0.f, q = 0.f;
    for (int r = r0; r < r1; r++) {
        float v = g_out[(size_t)r * DD + f];
        s += v; q += v * v;
    }
    atomicAdd(&g_bnsum[f], s);
    atomicAdd(&g_bnsq[f], q);
}

__global__ void k_bnfin(const float* __restrict__ gamma, const float* __restrict__ beta) {
    int f = threadIdx.x;
    float mu = g_bnsum[f] / (float)NN;
    float var = g_bnsq[f] / (float)NN - mu * mu;
    float rs = rsqrtf(var + EPSF);
    g_mu[f] = mu;
    g_rsg[f] = rs * gamma[f];
    g_bt[f] = beta[f];
}

__global__ void k_bnapply() {
    int t = blockIdx.x * blockDim.x + threadIdx.x;
    if (t >= NN * 32) return;
    int c = (t & 31) * 4;
    float4 o = ((const float4*)g_out)[t];
    float4 h = ((float4*)g_h)[t];
    o.x = fmaxf((o.x - g_mu[c + 0]) * g_rsg[c + 0] + g_bt[c + 0], 0.f) + h.x;
    o.y = fmaxf((o.y - g_mu[c + 1]) * g_rsg[c + 1] + g_bt[c + 1], 0.f) + h.y;
    o.z = fmaxf((o.z - g_mu[c + 2]) * g_rsg[c + 2] + g_bt[c + 2], 0.f) + h.z;
    o.w = fmaxf((o.w - g_mu[c + 3]) * g_rsg[c + 3] + g_bt[c + 3], 0.f) + h.w;
    ((float4*)g_h)[t] = o;
}

// ---------------- pooling + MLP ----------------
__global__ void k_pool() {
    int warp = (blockIdx.x * blockDim.x + threadIdx.x) >> 5;
    int lane = threadIdx.x & 31;
    if (warp >= NG) return;
    int beg = g_goff[warp], end = g_goff[warp + 1];
    float4 s = f4zero();
    const float4* hp = (const float4*)g_h;
    for (int r = beg; r < end; r++) {
        float4 v = hp[r * 32 + lane];
        s.x += v.x; s.y += v.y; s.z += v.z; s.w += v.w;
    }
    float inv = 1.f / (float)max(end - beg, 1);
    s.x *= inv; s.y *= inv; s.z *= inv; s.w *= inv;
    ((float4*)g_pool)[warp * 32 + lane] = s;
}

__global__ void k_mlp(const float* __restrict__ W1, const float* __restrict__ b1,
                      const float* __restrict__ W2, const float* __restrict__ b2,
                      const float* __restrict__ W3, const float* __restrict__ b3,
                      float* __restrict__ out) {
    __shared__ float sg[DD], sz1[64], sz2[32];
    int gid = blockIdx.x;
    int tid = threadIdx.x;      // 128
    sg[tid] = g_pool[gid * DD + tid];
    __syncthreads();
    if (tid < 64) {
        float a = b1[tid];
        for (int k = 0; k < DD; k++) a += sg[k] * W1[k * 64 + tid];
        sz1[tid] = fmaxf(a, 0.f);
    }
    __syncthreads();
    if (tid < 32) {
        float a = b2[tid];
        for (int k = 0; k < 64; k++) a += sz1[k] * W2[k * 32 + tid];
        sz2[tid] = fmaxf(a, 0.f);
    }
    __syncthreads();
    if (tid < NT) {
        float a = b3[tid];
        for (int k = 0; k < 32; k++) a += sz2[k] * W3[k * NT + tid];
        out[gid * NT + tid] = a;
    }
}

// ---------------- launch ----------------
extern "C" void kernel_launch(void* const* d_in, const int* in_sizes, int n_in,
                              void* d_out, int out_size) {
    const float* x      = (const float*)d_in[0];
    const int*   ei     = (const int*)d_in[1];
    const int*   batch  = (const int*)d_in[2];
    const float* emb_W  = (const float*)d_in[3];
    const float* emb_b  = (const float*)d_in[4];
    const float* conv_W = (const float*)d_in[5];
    const float* conv_b = (const float*)d_in[6];
    const float* bng    = (const float*)d_in[7];
    const float* bnb    = (const float*)d_in[8];
    const float* W1     = (const float*)d_in[9];
    const float* b1     = (const float*)d_in[10];
    const float* W2     = (const float*)d_in[11];
    const float* b2     = (const float*)d_in[12];
    const float* W3     = (const float*)d_in[13];
    const float* b3     = (const float*)d_in[14];
    float* out = (float*)d_out;

    k_zero<<<(NN + 255) / 256, 256>>>();
    k_hist<<<(NE + 255) / 256, 256>>>(ei, batch);
    k_scan<<<1, 1024>>>();
    k_delta<<<(NN + 255) / 256, 256>>>();
    k_scalars<<<(NN + 255) / 256, 256>>>();
    k_scatter<<<(NE + 255) / 256, 256>>>(ei);
    k_emb<<<(NN * 32 + 255) / 256, 256>>>(x, emb_W, emb_b);

    for (int l = 0; l < NL; l++) {
        k_agg<<<(NN * 32 + 255) / 256, 256>>>();
        k_gemm<<<(NN + BM - 1) / BM, 256>>>(conv_W + (size_t)l * 12 * DD * DD,
                                            conv_b + (size_t)l * DD);
        k_bnstats<<<(NN + 255) / 256, DD>>>();
        k_bnfin<<<1, DD>>>(bng + (size_t)l * DD, bnb + (size_t)l * DD);
        k_bnapply<<<(NN * 32 + 255) / 256, 256>>>();
    }

    k_pool<<<(NG * 32 + 255) / 256, 256>>>();
    k_mlp<<<NG, DD>>>(W1, b1, W2, b2, W3, b3, out);
}

// round 4
// speedup vs baseline: 2.4750x; 1.4903x over previous
#include <cuda_runtime.h>
#include <math.h>

#define NN 50000
#define NE 600000
#define DD 128
#define NL 4
#define NG 512
#define NT 10
#define EPSF 1e-5f

// ---------------- scratch (static device allocations) ----------------
__device__ int   g_deg[NN];
__device__ int   g_rowptr[NN + 1];
__device__ int   g_cursor[NN];
__device__ int   g_srcperm[NE];
__device__ float g_amp[NN], g_att[NN], g_dinv[NN];
__device__ float g_delta_acc;
__device__ float g_h[NN * DD];
__device__ float g_aggs[(size_t)NN * 4 * DD];   // [N][4*D] : mean|min|max|std
__device__ float g_out[NN * DD];
__device__ float g_bnsum[DD], g_bnsq[DD];
__device__ float g_mu[DD], g_rsg[DD], g_bt[DD];
__device__ int   g_gcnt[NG];
__device__ int   g_goff[NG + 1];
__device__ float g_pool[NG * DD];
__device__ unsigned g_Wt[(size_t)NL * DD * 1536];   // W transposed, tf32 bits: [l][n][k]

// ---------------- small helpers ----------------
__device__ __forceinline__ float4 f4zero() { return make_float4(0.f, 0.f, 0.f, 0.f); }

__device__ __forceinline__ unsigned f2tf(float f) {
    unsigned u;
    asm("cvt.rna.tf32.f32 %0, %1;" : "=r"(u) : "f"(f));
    return u;
}

__device__ __forceinline__ void cp_async16(unsigned smem_addr, const void* gptr) {
    asm volatile("cp.async.cg.shared.global [%0], [%1], 16;" :: "r"(smem_addr), "l"(gptr));
}
__device__ __forceinline__ void cp_commit() { asm volatile("cp.async.commit_group;"); }
__device__ __forceinline__ void cp_wait0() { asm volatile("cp.async.wait_group 0;"); }

// ---------------- setup kernels ----------------
__global__ void k_zero() {
    int i = blockIdx.x * blockDim.x + threadIdx.x;
    if (i < NN) { g_deg[i] = 0; g_cursor[i] = 0; }
    if (i < NG) g_gcnt[i] = 0;
    if (i == 0) g_delta_acc = 0.f;
}

__global__ void k_hist(const int* __restrict__ ei, const int* __restrict__ batch) {
    int e = blockIdx.x * blockDim.x + threadIdx.x;
    if (e < NE) atomicAdd(&g_deg[ei[NE + e]], 1);     // dst row
    if (e < NN) atomicAdd(&g_gcnt[batch[e]], 1);
}

__global__ void k_scan() {
    __shared__ int s[1024];
    int t = threadIdx.x;
    const int C = (NN + 1023) / 1024;
    int base = t * C;
    int acc = 0;
    for (int c = 0; c < C; c++) { int i = base + c; if (i < NN) acc += g_deg[i]; }
    s[t] = acc;
    __syncthreads();
    for (int d = 1; d < 1024; d <<= 1) {
        int add = (t >= d) ? s[t - d] : 0;
        __syncthreads();
        s[t] += add;
        __syncthreads();
    }
    int off = s[t] - acc;
    for (int c = 0; c < C; c++) { int i = base + c; if (i < NN) { g_rowptr[i] = off; off += g_deg[i]; } }
    if (t == 0) g_rowptr[NN] = NE;
    __syncthreads();
    int v = (t < NG) ? g_gcnt[t] : 0;
    s[t] = v;
    __syncthreads();
    for (int d = 1; d < 1024; d <<= 1) {
        int add = (t >= d) ? s[t - d] : 0;
        __syncthreads();
        s[t] += add;
        __syncthreads();
    }
    if (t < NG) g_goff[t] = s[t] - v;
    if (t == 0) g_goff[NG] = NN;
}

__global__ void k_delta() {
    int i = blockIdx.x * blockDim.x + threadIdx.x;
    float v = (i < NN) ? log1pf((float)g_deg[i]) : 0.f;
    for (int o = 16; o; o >>= 1) v += __shfl_down_sync(0xffffffffu, v, o);
    __shared__ float ws[8];
    if ((threadIdx.x & 31) == 0) ws[threadIdx.x >> 5] = v;
    __syncthreads();
    if (threadIdx.x < 8) {
        v = ws[threadIdx.x];
        for (int o = 4; o; o >>= 1) v += __shfl_down_sync(0xffu, v, o);
        if (threadIdx.x == 0) atomicAdd(&g_delta_acc, v);
    }
}

__global__ void k_scalars() {
    int i = blockIdx.x * blockDim.x + threadIdx.x;
    if (i >= NN) return;
    float deg = (float)g_deg[i];
    float d = fmaxf(deg, 1.f);
    float ld = log1pf(d);
    float delta = g_delta_acc / (float)NN;
    g_amp[i] = ld / delta;
    g_att[i] = delta / ld;
    g_dinv[i] = 1.f / d;
}

__global__ void k_scatter(const int* __restrict__ ei) {
    int e = blockIdx.x * blockDim.x + threadIdx.x;
    if (e >= NE) return;
    int dst = ei[NE + e];
    int p = atomicAdd(&g_cursor[dst], 1);
    g_srcperm[g_rowptr[dst] + p] = ei[e];
}

__global__ void k_emb(const float* __restrict__ x, const float* __restrict__ W,
                      const float* __restrict__ b) {
    int t = blockIdx.x * blockDim.x + threadIdx.x;
    int i = t >> 5, c = t & 31;
    if (i >= NN) return;
    float x0 = x[i * 3 + 0], x1 = x[i * 3 + 1], x2 = x[i * 3 + 2];
    float4 w0 = *(const float4*)&W[0 * DD + c * 4];
    float4 w1 = *(const float4*)&W[1 * DD + c * 4];
    float4 w2 = *(const float4*)&W[2 * DD + c * 4];
    float4 bb = *(const float4*)&b[c * 4];
    float4 h;
    h.x = bb.x + x0 * w0.x + x1 * w1.x + x2 * w2.x;
    h.y = bb.y + x0 * w0.y + x1 * w1.y + x2 * w2.y;
    h.z = bb.z + x0 * w0.z + x1 * w1.z + x2 * w2.z;
    h.w = bb.w + x0 * w0.w + x1 * w1.w + x2 * w2.w;
    ((float4*)g_h)[i * 32 + c] = h;
}

// Transpose + tf32-convert all conv weights: g_Wt[l][n][k] = cvt(W[l][k][n])
__global__ void k_wprep(const float* __restrict__ conv_W) {
    int t = blockIdx.x * blockDim.x + threadIdx.x;
    if (t >= NL * 1536 * DD) return;
    int l = t / (1536 * DD);
    int r = t - l * (1536 * DD);
    int k = r >> 7;           // r / DD
    int n = r & 127;          // coalesced read along n
    g_Wt[(size_t)l * DD * 1536 + n * 1536 + k] = f2tf(conv_W[t]);
}

// ---------------- per-layer kernels ----------------
__global__ void k_agg() {
    int warp = (blockIdx.x * blockDim.x + threadIdx.x) >> 5;
    int lane = threadIdx.x & 31;
    if (warp >= NN) return;
    int beg = g_rowptr[warp], end = g_rowptr[warp + 1];
    float4 s1 = f4zero(), s2 = f4zero();
    float4 mn = make_float4(INFINITY, INFINITY, INFINITY, INFINITY);
    float4 mx = make_float4(-INFINITY, -INFINITY, -INFINITY, -INFINITY);
    const float4* hp = (const float4*)g_h;
    for (int e = beg; e < end; e += 32) {
        int myj = (e + lane < end) ? g_srcperm[e + lane] : 0;
        int cnt = min(32, end - e);
#pragma unroll 4
        for (int kk = 0; kk < cnt; kk++) {
            int j = __shfl_sync(0xffffffffu, myj, kk);
            float4 m = hp[j * 32 + lane];
            s1.x += m.x; s1.y += m.y; s1.z += m.z; s1.w += m.w;
            s2.x += m.x * m.x; s2.y += m.y * m.y; s2.z += m.z * m.z; s2.w += m.w * m.w;
            mn.x = fminf(mn.x, m.x); mn.y = fminf(mn.y, m.y); mn.z = fminf(mn.z, m.z); mn.w = fminf(mn.w, m.w);
            mx.x = fmaxf(mx.x, m.x); mx.y = fmaxf(mx.y, m.y); mx.z = fmaxf(mx.z, m.z); mx.w = fmaxf(mx.w, m.w);
        }
    }
    float dinv = g_dinv[warp];
    float4 mean, sd;
    mean.x = s1.x * dinv; mean.y = s1.y * dinv; mean.z = s1.z * dinv; mean.w = s1.w * dinv;
    sd.x = sqrtf(fmaxf(s2.x * dinv - mean.x * mean.x, 0.f) + EPSF);
    sd.y = sqrtf(fmaxf(s2.y * dinv - mean.y * mean.y, 0.f) + EPSF);
    sd.z = sqrtf(fmaxf(s2.z * dinv - mean.z * mean.z, 0.f) + EPSF);
    sd.w = sqrtf(fmaxf(s2.w * dinv - mean.w * mean.w, 0.f) + EPSF);
    if (beg == end) { mn = f4zero(); mx = f4zero(); }
    float4* A = (float4*)(g_aggs + (size_t)warp * 4 * DD);
    A[0 * 32 + lane] = mean;
    A[1 * 32 + lane] = mn;
    A[2 * 32 + lane] = mx;
    A[3 * 32 + lane] = sd;
}

// ---------------- TF32 tensor-core GEMM, double-buffered + cp.async B ----------------
#define BM 128
#define BK 16
#define SSTRIDE 20          // 16 + 4 pad
#define NCHUNK 96           // 1536 / BK

__global__ __launch_bounds__(256, 2) void k_gemm(const unsigned* __restrict__ Wt,
                                                 const float* __restrict__ bl) {
    __shared__ unsigned sA[2][BM * SSTRIDE];
    __shared__ unsigned sB[2][DD * SSTRIDE];
    __shared__ float sAmp[BM], sAtt[BM], sBias[DD];

    int bm = blockIdx.x * BM;
    int tid = threadIdx.x;
    int lane = tid & 31;
    int warp = tid >> 5;
    int g = lane >> 2;
    int t = lane & 3;
    int m_base = (warp >> 2) * 64;
    int n_base = (warp & 3) * 32;

    if (tid < BM) {
        int r = bm + tid;
        sAmp[tid] = (r < NN) ? g_amp[r] : 0.f;
        sAtt[tid] = (r < NN) ? g_att[r] : 0.f;
        sBias[tid] = bl[tid];
    }
    if (blockIdx.x == 0 && tid < DD) { g_bnsum[tid] = 0.f; g_bnsq[tid] = 0.f; }
    __syncthreads();

    float acc[4][4][4];
#pragma unroll
    for (int i = 0; i < 4; i++)
#pragma unroll
        for (int j = 0; j < 4; j++)
#pragma unroll
            for (int c = 0; c < 4; c++) acc[i][j][c] = 0.f;

    // A staging descriptors: thread covers rows aM0, aM0+64 at k-words aK..aK+3
    const int aM0 = tid >> 2;
    const int aK = (tid & 3) * 4;
    // B cp.async descriptors: rows n0, n0+64 at k-words bK..bK+3
    const int n0 = tid >> 2;
    const int bK = (tid & 3) * 4;

    float4 aR[2];

    auto loadA = [&](int chunk) {
        int koff = (chunk * BK) & 511;
#pragma unroll
        for (int u = 0; u < 2; u++) {
            int row = bm + aM0 + u * 64;
            aR[u] = (row < NN)
                ? *(const float4*)&g_aggs[(size_t)row * 512 + koff + aK]
                : f4zero();
        }
    };
    auto storeA = [&](int chunk, int buf) {
        int slab = (chunk * BK) >> 9;
#pragma unroll
        for (int u = 0; u < 2; u++) {
            int m = aM0 + u * 64;
            float sc = (slab == 0) ? 1.f : ((slab == 1) ? sAmp[m] : sAtt[m]);
            unsigned* pa = &sA[buf][m * SSTRIDE + aK];
            pa[0] = f2tf(aR[u].x * sc);
            pa[1] = f2tf(aR[u].y * sc);
            pa[2] = f2tf(aR[u].z * sc);
            pa[3] = f2tf(aR[u].w * sc);
        }
    };
    auto cpB = [&](int chunk, int buf) {
        int kg0 = chunk * BK;
#pragma unroll
        for (int u = 0; u < 2; u++) {
            int n = n0 + u * 64;
            unsigned dst = (unsigned)__cvta_generic_to_shared(&sB[buf][n * SSTRIDE + bK]);
            cp_async16(dst, &Wt[(size_t)n * 1536 + kg0 + bK]);
        }
    };
    auto mmaChunk = [&](int buf) {
#pragma unroll
        for (int ks = 0; ks < BK; ks += 8) {
            unsigned bfrag[4][2];
#pragma unroll
            for (int j = 0; j < 4; j++) {
                int n = n_base + j * 8 + g;
                bfrag[j][0] = sB[buf][n * SSTRIDE + ks + t];
                bfrag[j][1] = sB[buf][n * SSTRIDE + ks + t + 4];
            }
#pragma unroll
            for (int i = 0; i < 4; i++) {
                int m0 = m_base + i * 16 + g;
                unsigned a0 = sA[buf][m0 * SSTRIDE + ks + t];
                unsigned a1 = sA[buf][(m0 + 8) * SSTRIDE + ks + t];
                unsigned a2 = sA[buf][m0 * SSTRIDE + ks + t + 4];
                unsigned a3 = sA[buf][(m0 + 8) * SSTRIDE + ks + t + 4];
#pragma unroll
                for (int j = 0; j < 4; j++) {
                    asm volatile(
                        "mma.sync.aligned.m16n8k8.row.col.f32.tf32.tf32.f32 "
                        "{%0,%1,%2,%3}, {%4,%5,%6,%7}, {%8,%9}, {%0,%1,%2,%3};"
                        : "+f"(acc[i][j][0]), "+f"(acc[i][j][1]),
                          "+f"(acc[i][j][2]), "+f"(acc[i][j][3])
                        : "r"(a0), "r"(a1), "r"(a2), "r"(a3),
                          "r"(bfrag[j][0]), "r"(bfrag[j][1]));
                }
            }
        }
    };

    // prologue
    loadA(0);
    cpB(0, 0);
    cp_commit();
    storeA(0, 0);
    cp_wait0();
    __syncthreads();

    for (int c = 0; c < NCHUNK; c++) {
        int cur = c & 1;
        if (c + 1 < NCHUNK) {
            loadA(c + 1);
            cpB(c + 1, cur ^ 1);
            cp_commit();
        }
        mmaChunk(cur);
        if (c + 1 < NCHUNK) storeA(c + 1, cur ^ 1);
        cp_wait0();
        __syncthreads();
    }

    // epilogue: add bias, store
#pragma unroll
    for (int i = 0; i < 4; i++) {
        int r0 = bm + m_base + i * 16 + g;
        int r1 = r0 + 8;
#pragma unroll
        for (int j = 0; j < 4; j++) {
            int col = n_base + j * 8 + t * 2;
            float bx = sBias[col], by = sBias[col + 1];
            if (r0 < NN) {
                float2 v = make_float2(acc[i][j][0] + bx, acc[i][j][1] + by);
                *(float2*)&g_out[(size_t)r0 * DD + col] = v;
            }
            if (r1 < NN) {
                float2 v = make_float2(acc[i][j][2] + bx, acc[i][j][3] + by);
                *(float2*)&g_out[(size_t)r1 * DD + col] = v;
            }
        }
    }
}

__global__ void k_bnstats() {
    int f = threadIdx.x;            // 128 threads
    int r0 = blockIdx.x * 256;
    int r1 = min(r0 + 256, NN);
    float s = 0.f, q = 0.f;
    for (int r = r0; r < r1; r++) {
        float v = g_out[(size_t)r * DD + f];
        s += v; q += v * v;
    }
    atomicAdd(&g_bnsum[f], s);
    atomicAdd(&g_bnsq[f], q);
}

__global__ void k_bnfin(const float* __restrict__ gamma, const float* __restrict__ beta) {
    int f = threadIdx.x;
    float mu = g_bnsum[f] / (float)NN;
    float var = g_bnsq[f] / (float)NN - mu * mu;
    float rs = rsqrtf(var + EPSF);
    g_mu[f] = mu;
    g_rsg[f] = rs * gamma[f];
    g_bt[f] = beta[f];
}

__global__ void k_bnapply() {
    int t = blockIdx.x * blockDim.x + threadIdx.x;
    if (t >= NN * 32) return;
    int c = (t & 31) * 4;
    float4 o = ((const float4*)g_out)[t];
    float4 h = ((float4*)g_h)[t];
    o.x = fmaxf((o.x - g_mu[c + 0]) * g_rsg[c + 0] + g_bt[c + 0], 0.f) + h.x;
    o.y = fmaxf((o.y - g_mu[c + 1]) * g_rsg[c + 1] + g_bt[c + 1], 0.f) + h.y;
    o.z = fmaxf((o.z - g_mu[c + 2]) * g_rsg[c + 2] + g_bt[c + 2], 0.f) + h.z;
    o.w = fmaxf((o.w - g_mu[c + 3]) * g_rsg[c + 3] + g_bt[c + 3], 0.f) + h.w;
    ((float4*)g_h)[t] = o;
}

// ---------------- pooling + MLP ----------------
__global__ void k_pool() {
    int warp = (blockIdx.x * blockDim.x + threadIdx.x) >> 5;
    int lane = threadIdx.x & 31;
    if (warp >= NG) return;
    int beg = g_goff[warp], end = g_goff[warp + 1];
    float4 s = f4zero();
    const float4* hp = (const float4*)g_h;
    for (int r = beg; r < end; r++) {
        float4 v = hp[r * 32 + lane];
        s.x += v.x; s.y += v.y; s.z += v.z; s.w += v.w;
    }
    float inv = 1.f / (float)max(end - beg, 1);
    s.x *= inv; s.y *= inv; s.z *= inv; s.w *= inv;
    ((float4*)g_pool)[warp * 32 + lane] = s;
}

__global__ void k_mlp(const float* __restrict__ W1, const float* __restrict__ b1,
                      const float* __restrict__ W2, const float* __restrict__ b2,
                      const float* __restrict__ W3, const float* __restrict__ b3,
                      float* __restrict__ out) {
    __shared__ float sg[DD], sz1[64], sz2[32];
    int gid = blockIdx.x;
    int tid = threadIdx.x;      // 128
    sg[tid] = g_pool[gid * DD + tid];
    __syncthreads();
    if (tid < 64) {
        float a = b1[tid];
        for (int k = 0; k < DD; k++) a += sg[k] * W1[k * 64 + tid];
        sz1[tid] = fmaxf(a, 0.f);
    }
    __syncthreads();
    if (tid < 32) {
        float a = b2[tid];
        for (int k = 0; k < 64; k++) a += sz1[k] * W2[k * 32 + tid];
        sz2[tid] = fmaxf(a, 0.f);
    }
    __syncthreads();
    if (tid < NT) {
        float a = b3[tid];
        for (int k = 0; k < 32; k++) a += sz2[k] * W3[k * NT + tid];
        out[gid * NT + tid] = a;
    }
}

// ---------------- launch ----------------
extern "C" void kernel_launch(void* const* d_in, const int* in_sizes, int n_in,
                              void* d_out, int out_size) {
    const float* x      = (const float*)d_in[0];
    const int*   ei     = (const int*)d_in[1];
    const int*   batch  = (const int*)d_in[2];
    const float* emb_W  = (const float*)d_in[3];
    const float* emb_b  = (const float*)d_in[4];
    const float* conv_W = (const float*)d_in[5];
    const float* conv_b = (const float*)d_in[6];
    const float* bng    = (const float*)d_in[7];
    const float* bnb    = (const float*)d_in[8];
    const float* W1     = (const float*)d_in[9];
    const float* b1     = (const float*)d_in[10];
    const float* W2     = (const float*)d_in[11];
    const float* b2     = (const float*)d_in[12];
    const float* W3     = (const float*)d_in[13];
    const float* b3     = (const float*)d_in[14];
    float* out = (float*)d_out;

    k_zero<<<(NN + 255) / 256, 256>>>();
    k_hist<<<(NE + 255) / 256, 256>>>(ei, batch);
    k_scan<<<1, 1024>>>();
    k_delta<<<(NN + 255) / 256, 256>>>();
    k_scalars<<<(NN + 255) / 256, 256>>>();
    k_scatter<<<(NE + 255) / 256, 256>>>(ei);
    k_emb<<<(NN * 32 + 255) / 256, 256>>>(x, emb_W, emb_b);
    k_wprep<<<(NL * 1536 * DD + 255) / 256, 256>>>(conv_W);

    unsigned* g_Wt_ptr;
    cudaGetSymbolAddress((void**)&g_Wt_ptr, g_Wt);

    for (int l = 0; l < NL; l++) {
        k_agg<<<(NN * 32 + 255) / 256, 256>>>();
        k_gemm<<<(NN + BM - 1) / BM, 256>>>(g_Wt_ptr + (size_t)l * DD * 1536,
                                            conv_b + (size_t)l * DD);
        k_bnstats<<<(NN + 255) / 256, DD>>>();
        k_bnfin<<<1, DD>>>(bng + (size_t)l * DD, bnb + (size_t)l * DD);
        k_bnapply<<<(NN * 32 + 255) / 256, 256>>>();
    }

    k_pool<<<(NG * 32 + 255) / 256, 256>>>();
    k_mlp<<<NG, DD>>>(W1, b1, W2, b2, W3, b3, out);
}